// round 12
// baseline (speedup 1.0000x reference)
#include <cuda_runtime.h>
#include <cuda_fp16.h>
#include <cstdint>

// Problem constants (fixed by the dataset)
#define NN   100000       // nodes
#define NE   1600000      // edges (excluding self loops)
#define FD   128          // feature / hidden dim
#define NC   64           // classes
#define NB_SCAN 98        // ceil(NN / 1024), all blocks co-resident (<148 SMs)
#define NTILES 782        // ceil(NN / 128)
#define GEMM_GRID 296     // 2 CTAs/SM * 148 SMs

// ---------------- scratch (device globals; no allocation allowed) ----------
__device__ __half g_xh[NN * FD];     // x converted to fp16 (GEMM-1 input)
__device__ __half g_bufh[NN * FD];   // GEMM output h (fp16, gather operand)
__device__ __half g_bufact[NN * FD]; // agg+relu output (fp16, GEMM input)
__device__ float  g_dinv[NN];
__device__ int    g_deg[NN];         // in-degree (without self loop)
__device__ int    g_rowstart[NN];    // exclusive prefix of deg
__device__ int    g_cursor[NN];
__device__ int2   g_pair[NE];        // (src, norm-bits) per edge, grouped by dst
__device__ int    g_status[NB_SCAN]; // lookback scan status (memset to 0)
__device__ int    g_sync;            // grid-sync counter (memset to 0)

__device__ __forceinline__ uint32_t pack_h2(float x, float y)
{
    __half2 h = __floats2half2_rn(x, y);
    return *reinterpret_cast<uint32_t*>(&h);
}

// ------------- fused preprocessing: count + cvt + grid-sync + scan ---------
// 98 blocks x 1024 threads, all co-resident -> spin grid-sync is safe.
__global__ void __launch_bounds__(1024) k_pre(const int* __restrict__ ei,
                                              const float4* __restrict__ x,
                                              uint2* __restrict__ xh)
{
    const int tid = threadIdx.x;
    const int gid = blockIdx.x * 1024 + tid;
    const int gstride = NB_SCAN * 1024;           // 100352

    // phase A: degree histogram
    for (int e = gid; e < NE; e += gstride) {
        int d = ei[NE + e];
        atomicAdd(&g_deg[d], 1);
    }
    // phase B: x -> fp16 (independent of phase A)
    for (int i = gid; i < NN * 32; i += gstride) {
        float4 v = __ldg(&x[i]);
        uint2 p;
        p.x = pack_h2(v.x, v.y);
        p.y = pack_h2(v.z, v.w);
        xh[i] = p;
    }

    // grid sync: all degree atomics visible before scan
    __threadfence();
    __syncthreads();
    if (tid == 0) {
        atomicAdd(&g_sync, 1);
        while (atomicAdd(&g_sync, 0) < NB_SCAN) {}
    }
    __syncthreads();

    // phase C: scan over g_deg -> g_rowstart (exclusive) + dinv
    __shared__ int s[1024];
    __shared__ int sh_prefix;
    int i = blockIdx.x * 1024 + tid;
    int v = (i < NN) ? g_deg[i] : 0;
    s[tid] = v;
    __syncthreads();
    #pragma unroll
    for (int off = 1; off < 1024; off <<= 1) {
        int add = (tid >= off) ? s[tid - off] : 0;
        __syncthreads();
        s[tid] += add;
        __syncthreads();
    }
    if (tid == 1023) {
        int total = s[tid];
        __threadfence();
        atomicExch(&g_status[blockIdx.x], total | 0x40000000);
    }
    if (tid == 0) {
        int p = 0;
        for (int j = 0; j < (int)blockIdx.x; j++) {
            int st;
            do { st = atomicAdd(&g_status[j], 0); } while (!(st & 0x40000000));
            p += st & 0x3FFFFFFF;
        }
        sh_prefix = p;
    }
    __syncthreads();
    if (i < NN) {
        g_rowstart[i] = s[tid] - v + sh_prefix;
        g_dinv[i] = rsqrtf((float)v + 1.0f);      // +1 = self loop
    }
}

__global__ void k_fill(const int* __restrict__ ei)
{
    int e = blockIdx.x * blockDim.x + threadIdx.x;
    if (e < NE) {
        int s = ei[e];
        int d = ei[NE + e];
        int p = g_rowstart[d] + atomicAdd(&g_cursor[d], 1);
        float nm = __ldg(&g_dinv[s]) * __ldg(&g_dinv[d]);
        g_pair[p] = make_int2(s, __float_as_int(nm));
    }
}

// ---------------- fp16 MMA helper ------------------------------------------
__device__ __forceinline__ void mma_f16(
    float& d0, float& d1, float& d2, float& d3,
    uint32_t a0, uint32_t a1, uint32_t a2, uint32_t a3,
    uint32_t b0, uint32_t b1)
{
    asm volatile(
        "mma.sync.aligned.m16n8k16.row.col.f32.f16.f16.f32 "
        "{%0,%1,%2,%3}, {%4,%5,%6,%7}, {%8,%9}, {%0,%1,%2,%3};"
        : "+f"(d0), "+f"(d1), "+f"(d2), "+f"(d3)
        : "r"(a0), "r"(a1), "r"(a2), "r"(a3), "r"(b0), "r"(b1));
}

// ---------------- GEMM: C[NN, OUT] = A[NN,128] @ W[OUT,128]^T (+bias) ------
// Persistent multi-tile fp16 MMA GEMM with cp.async double-buffered A tiles.
template <int OUT, bool HOUT>
__global__ void __launch_bounds__(256, 2) k_gemm(
    const __half* __restrict__ A, const float* __restrict__ W,
    const float* __restrict__ bias, void* __restrict__ Cv)
{
    constexpr int NA = OUT / 16;          // n-atoms per warp (8 or 4)
    constexpr int XWORDS = 128 * 68;
    extern __shared__ uint32_t sm[];      // half2 units
    uint32_t* Xstage[2] = { sm, sm + XWORDS };
    uint32_t* Ws = sm + 2 * XWORDS;       // [OUT][68]
    const int tid  = threadIdx.x;
    const int warp = tid >> 5;
    const int lane = tid & 31;

    const int m_off = (warp >> 1) * 32;        // 0,32,64,96
    const int n_off = (warp & 1) * (OUT / 2);  // 0, OUT/2
    const int gid = lane >> 2;                 // group id 0..7
    const int tig = lane & 3;                  // thread in group 0..3

    auto fill_async = [&](uint32_t* Xs, int t) {
        int row0 = t * 128;
        #pragma unroll
        for (int i = 0; i < 8; i++) {
            int idx = tid + i * 256;
            int r = idx >> 4, c8 = idx & 15;
            uint32_t dst = (uint32_t)__cvta_generic_to_shared(&Xs[r * 68 + c8 * 4]);
            const void* src = (const char*)A + ((size_t)(row0 + r) * 128 + c8 * 8) * 2;
            int sz = (row0 + r < NN) ? 16 : 0;
            asm volatile("cp.async.cg.shared.global [%0], [%1], 16, %2;"
                         :: "r"(dst), "l"(src), "r"(sz));
        }
        asm volatile("cp.async.commit_group;");
    };

    int tile = blockIdx.x;
    if (tile < NTILES) fill_async(Xstage[0], tile);

    for (int idx = tid; idx < OUT * 32; idx += 256) {
        int j = idx >> 5, c4 = idx & 31;
        float4 v = reinterpret_cast<const float4*>(W)[idx];
        uint2 p;
        p.x = pack_h2(v.x, v.y);
        p.y = pack_h2(v.z, v.w);
        *reinterpret_cast<uint2*>(&Ws[j * 68 + c4 * 2]) = p;
    }

    int stage = 0;
    for (; tile < NTILES; tile += GEMM_GRID) {
        int next = tile + GEMM_GRID;
        if (next < NTILES) {
            fill_async(Xstage[stage ^ 1], next);
            asm volatile("cp.async.wait_group 1;");
        } else {
            asm volatile("cp.async.wait_group 0;");
        }
        __syncthreads();
        const uint32_t* Xs = Xstage[stage];
        const int row0 = tile * 128;

        float acc[2][NA][4];
        #pragma unroll
        for (int ma = 0; ma < 2; ma++)
            #pragma unroll
            for (int na = 0; na < NA; na++)
                #pragma unroll
                for (int c = 0; c < 4; c++) acc[ma][na][c] = 0.f;

        #pragma unroll
        for (int ks = 0; ks < 8; ks++) {
            uint32_t a[2][4];
            #pragma unroll
            for (int ma = 0; ma < 2; ma++) {
                int row = m_off + ma * 16 + gid;
                a[ma][0] = Xs[row * 68 + ks * 8 + tig];
                a[ma][1] = Xs[(row + 8) * 68 + ks * 8 + tig];
                a[ma][2] = Xs[row * 68 + ks * 8 + tig + 4];
                a[ma][3] = Xs[(row + 8) * 68 + ks * 8 + tig + 4];
            }
            #pragma unroll
            for (int na = 0; na < NA; na++) {
                int n = n_off + na * 8 + gid;
                uint32_t b0 = Ws[n * 68 + ks * 8 + tig];
                uint32_t b1 = Ws[n * 68 + ks * 8 + tig + 4];
                #pragma unroll
                for (int ma = 0; ma < 2; ma++) {
                    float* d = acc[ma][na];
                    mma_f16(d[0], d[1], d[2], d[3],
                            a[ma][0], a[ma][1], a[ma][2], a[ma][3], b0, b1);
                }
            }
        }

        #pragma unroll
        for (int ma = 0; ma < 2; ma++) {
            #pragma unroll
            for (int na = 0; na < NA; na++) {
                int col = n_off + na * 8 + 2 * tig;
                float bx = 0.f, by = 0.f;
                if (bias) { bx = __ldg(&bias[col]); by = __ldg(&bias[col + 1]); }
                int r0 = row0 + m_off + ma * 16 + gid;
                int r1 = r0 + 8;
                if (HOUT) {
                    __half* C = (__half*)Cv;
                    if (r0 < NN)
                        *reinterpret_cast<__half2*>(&C[(size_t)r0 * OUT + col]) =
                            __floats2half2_rn(acc[ma][na][0] + bx, acc[ma][na][1] + by);
                    if (r1 < NN)
                        *reinterpret_cast<__half2*>(&C[(size_t)r1 * OUT + col]) =
                            __floats2half2_rn(acc[ma][na][2] + bx, acc[ma][na][3] + by);
                } else {
                    float* C = (float*)Cv;
                    if (r0 < NN)
                        *reinterpret_cast<float2*>(&C[(size_t)r0 * OUT + col]) =
                            make_float2(acc[ma][na][0] + bx, acc[ma][na][1] + by);
                    if (r1 < NN)
                        *reinterpret_cast<float2*>(&C[(size_t)r1 * OUT + col]) =
                            make_float2(acc[ma][na][2] + bx, acc[ma][na][3] + by);
                }
            }
        }
        __syncthreads();
        stage ^= 1;
    }
}

// -------- aggregation + self-loop + bias + ReLU fused: warp per node -------
// LDG.128 gather: lanes 0-15 handle even edge, 16-31 odd edge of each pair;
// each lane loads 16B (8 dims). 8 LDG.128 = 16 edges in flight, no serial
// tail (out-of-range lanes carry (src=0, norm=0) pairs -> contribute 0).
// Final shfl_xor(16) merges the two edge-parity partial sums.
__global__ void k_agg_relu(const __half* __restrict__ h,
                           const float* __restrict__ bias,
                           __half* __restrict__ out)
{
    int gw = (blockIdx.x * blockDim.x + threadIdx.x) >> 5;   // node id
    if (gw >= NN) return;
    const int lane = threadIdx.x & 31;
    const int half = lane >> 4;          // edge parity handled by this lane
    const int sub  = lane & 15;          // 16B chunk within the 256B row
    const int beg = g_rowstart[gw];
    const int cnt = g_deg[gw];
    const uint4* hp = reinterpret_cast<const uint4*>(h);     // 16 uint4 / row

    float acc[8];
    #pragma unroll
    for (int d = 0; d < 8; d++) acc[d] = 0.f;

    for (int t0 = 0; t0 < cnt; t0 += 32) {
        int2 pr = make_int2(0, 0);                 // src=0, norm=0 (inert)
        if (t0 + lane < cnt) pr = __ldg(&g_pair[beg + t0 + lane]);
        int m = min(32, cnt - t0);
        #pragma unroll
        for (int g = 0; g < 2; g++) {
            if (g * 16 >= m) break;
            uint4 u[8];
            float nrm[8];
            #pragma unroll
            for (int q = 0; q < 8; q++) {
                int eidx = g * 16 + 2 * q + half;  // per-lane edge index
                int src  = __shfl_sync(0xFFFFFFFFu, pr.x, eidx);
                nrm[q]   = __int_as_float(__shfl_sync(0xFFFFFFFFu, pr.y, eidx));
                u[q]     = __ldg(&hp[(size_t)src * 16 + sub]);
            }
            #pragma unroll
            for (int q = 0; q < 8; q++) {
                float2 f0 = __half22float2(*reinterpret_cast<__half2*>(&u[q].x));
                float2 f1 = __half22float2(*reinterpret_cast<__half2*>(&u[q].y));
                float2 f2 = __half22float2(*reinterpret_cast<__half2*>(&u[q].z));
                float2 f3 = __half22float2(*reinterpret_cast<__half2*>(&u[q].w));
                acc[0] += nrm[q] * f0.x; acc[1] += nrm[q] * f0.y;
                acc[2] += nrm[q] * f1.x; acc[3] += nrm[q] * f1.y;
                acc[4] += nrm[q] * f2.x; acc[5] += nrm[q] * f2.y;
                acc[6] += nrm[q] * f3.x; acc[7] += nrm[q] * f3.y;
            }
        }
    }

    // merge the two edge-parity halves: lane l <-> lane l^16 hold same dims
    #pragma unroll
    for (int d = 0; d < 8; d++)
        acc[d] += __shfl_xor_sync(0xFFFFFFFFu, acc[d], 16);

    // self-loop + bias + ReLU; lanes 0-15 write the row
    float dinv_d = g_dinv[gw];
    float c = dinv_d * dinv_d;
    uint4 us = __ldg(&hp[(size_t)gw * 16 + sub]);
    float2 s0 = __half22float2(*reinterpret_cast<__half2*>(&us.x));
    float2 s1 = __half22float2(*reinterpret_cast<__half2*>(&us.y));
    float2 s2 = __half22float2(*reinterpret_cast<__half2*>(&us.z));
    float2 s3 = __half22float2(*reinterpret_cast<__half2*>(&us.w));
    const float4* b4 = reinterpret_cast<const float4*>(bias);
    float4 ba = __ldg(&b4[sub * 2]);
    float4 bb = __ldg(&b4[sub * 2 + 1]);
    float r0 = fmaxf(acc[0] + c * s0.x + ba.x, 0.f);
    float r1 = fmaxf(acc[1] + c * s0.y + ba.y, 0.f);
    float r2 = fmaxf(acc[2] + c * s1.x + ba.z, 0.f);
    float r3 = fmaxf(acc[3] + c * s1.y + ba.w, 0.f);
    float r4 = fmaxf(acc[4] + c * s2.x + bb.x, 0.f);
    float r5 = fmaxf(acc[5] + c * s2.y + bb.y, 0.f);
    float r6 = fmaxf(acc[6] + c * s3.x + bb.z, 0.f);
    float r7 = fmaxf(acc[7] + c * s3.y + bb.w, 0.f);
    if (lane < 16) {
        uint4 o;
        o.x = pack_h2(r0, r1);
        o.y = pack_h2(r2, r3);
        o.z = pack_h2(r4, r5);
        o.w = pack_h2(r6, r7);
        reinterpret_cast<uint4*>(out)[(size_t)gw * 16 + sub] = o;
    }
}

// ---------------- launcher --------------------------------------------------
extern "C" void kernel_launch(void* const* d_in, const int* in_sizes, int n_in,
                              void* d_out, int out_size)
{
    (void)in_sizes; (void)n_in; (void)out_size;
    const float* x  = (const float*)d_in[0];
    const int*   ei = (const int*)d_in[1];          // int32 (JAX x64 disabled)
    const float* W1 = (const float*)d_in[2];
    const float* b1 = (const float*)d_in[3];
    const float* W2 = (const float*)d_in[4];
    const float* b2 = (const float*)d_in[5];
    const float* Wl = (const float*)d_in[6];
    const float* bl = (const float*)d_in[7];
    float* out = (float*)d_out;

    void *pxh, *pbh, *pba, *pdeg, *pcur, *pst, *psy;
    cudaGetSymbolAddress(&pxh, g_xh);
    cudaGetSymbolAddress(&pbh, g_bufh);
    cudaGetSymbolAddress(&pba, g_bufact);
    cudaGetSymbolAddress(&pdeg, g_deg);
    cudaGetSymbolAddress(&pcur, g_cursor);
    cudaGetSymbolAddress(&pst,  g_status);
    cudaGetSymbolAddress(&psy,  g_sync);
    __half* xh = (__half*)pxh;
    __half* bufh = (__half*)pbh;
    __half* bufact = (__half*)pba;

    const int SMEM128 = (2 * 128 * 68 + 128 * 68) * 4;   // 104448 B
    const int SMEM64  = (2 * 128 * 68 + 64 * 68) * 4;    // 87040 B
    cudaFuncSetAttribute((const void*)k_gemm<128, true>,
                         cudaFuncAttributeMaxDynamicSharedMemorySize, SMEM128);
    cudaFuncSetAttribute((const void*)k_gemm<64, false>,
                         cudaFuncAttributeMaxDynamicSharedMemorySize, SMEM64);

    const int TB = 256;
    const int GB_E = (NE + TB - 1) / TB;           // 6250
    const int GB_W = (NN * 32 + TB - 1) / TB;      // 12500 (warp per node)

    // --- zero-init via memset nodes (not kernel launches) ---
    cudaMemsetAsync(pdeg, 0, NN * sizeof(int));
    cudaMemsetAsync(pcur, 0, NN * sizeof(int));
    cudaMemsetAsync(pst,  0, NB_SCAN * sizeof(int));
    cudaMemsetAsync(psy,  0, sizeof(int));

    // --- preprocessing: fused count+cvt+scan (1), fill (2) ---
    k_pre<<<NB_SCAN, 1024>>>(ei, (const float4*)x, (uint2*)xh);
    k_fill<<<GB_E, TB>>>(ei);

    // --- layer 1: gemm (3), agg (4 <- profiled slot) ---
    k_gemm<128, true><<<GEMM_GRID, TB, SMEM128>>>(xh, W1, nullptr, bufh);
    k_agg_relu<<<GB_W, TB>>>(bufh, b1, bufact);

    // --- layer 2 ---
    k_gemm<128, true><<<GEMM_GRID, TB, SMEM128>>>(bufact, W2, nullptr, bufh);
    k_agg_relu<<<GB_W, TB>>>(bufh, b2, bufact);

    // --- readout ---
    k_gemm<64, false><<<GEMM_GRID, TB, SMEM64>>>(bufact, Wl, bl, out);
}

// round 13
// speedup vs baseline: 1.1458x; 1.1458x over previous
#include <cuda_runtime.h>
#include <cuda_fp16.h>
#include <cstdint>

// Problem constants (fixed by the dataset)
#define NN   100000       // nodes
#define NE   1600000      // edges (excluding self loops)
#define FD   128          // feature / hidden dim
#define NC   64           // classes
#define NB_SCAN 98        // ceil(NN / 1024), all blocks co-resident (<148 SMs)
#define NTILES 782        // ceil(NN / 128)
#define GEMM_GRID 296     // 2 CTAs/SM * 148 SMs

// ---------------- scratch (device globals; no allocation allowed) ----------
__device__ __half g_xh[NN * FD];     // x converted to fp16 (GEMM-1 input)
__device__ __half g_bufh[NN * FD];   // GEMM output h (fp16, gather operand)
__device__ __half g_bufact[NN * FD]; // agg+relu output (fp16, GEMM input)
__device__ float  g_dinv[NN];
__device__ int    g_deg[NN];         // in-degree (without self loop)
__device__ int    g_rowstart[NN];    // exclusive prefix of deg
__device__ int    g_cursor[NN];
__device__ int2   g_pair[NE];        // (src, norm-bits) per edge, grouped by dst
__device__ int    g_status[NB_SCAN]; // lookback scan status (memset to 0)

__device__ __forceinline__ uint32_t pack_h2(float x, float y)
{
    __half2 h = __floats2half2_rn(x, y);
    return *reinterpret_cast<uint32_t*>(&h);
}

// ---------------- preprocessing kernels ------------------------------------

// Fused: degree count (threads < NE) + x -> fp16 conversion (all 3.2M threads).
__global__ void k_count_cvt(const int* __restrict__ ei,
                            const float4* __restrict__ x,
                            uint2* __restrict__ xh)
{
    int i = blockIdx.x * blockDim.x + threadIdx.x;
    if (i < NE) {
        int d = ei[NE + i];
        atomicAdd(&g_deg[d], 1);
    }
    float4 v = __ldg(&x[i]);
    uint2 p;
    p.x = pack_h2(v.x, v.y);
    p.y = pack_h2(v.z, v.w);
    xh[i] = p;
}

// Single-pass scan over g_deg -> g_rowstart (exclusive), plus dinv.
__global__ void __launch_bounds__(1024) k_scan()
{
    __shared__ int s[1024];
    __shared__ int sh_prefix;
    int t = threadIdx.x;
    int i = blockIdx.x * 1024 + t;
    int v = (i < NN) ? g_deg[i] : 0;
    s[t] = v;
    __syncthreads();
    #pragma unroll
    for (int off = 1; off < 1024; off <<= 1) {
        int add = (t >= off) ? s[t - off] : 0;
        __syncthreads();
        s[t] += add;
        __syncthreads();
    }
    if (t == 1023) {
        int total = s[t];
        __threadfence();
        atomicExch(&g_status[blockIdx.x], total | 0x40000000);
    }
    if (t == 0) {
        int p = 0;
        for (int j = 0; j < (int)blockIdx.x; j++) {
            int st;
            do { st = atomicAdd(&g_status[j], 0); } while (!(st & 0x40000000));
            p += st & 0x3FFFFFFF;
        }
        sh_prefix = p;
    }
    __syncthreads();
    if (i < NN) {
        g_rowstart[i] = s[t] - v + sh_prefix;
        g_dinv[i] = rsqrtf((float)v + 1.0f);    // +1 = self loop
    }
}

__global__ void k_fill(const int* __restrict__ ei)
{
    int e = blockIdx.x * blockDim.x + threadIdx.x;
    if (e < NE) {
        int s = ei[e];
        int d = ei[NE + e];
        int p = g_rowstart[d] + atomicAdd(&g_cursor[d], 1);
        float nm = __ldg(&g_dinv[s]) * __ldg(&g_dinv[d]);
        g_pair[p] = make_int2(s, __float_as_int(nm));
    }
}

// ---------------- fp16 MMA helper ------------------------------------------
__device__ __forceinline__ void mma_f16(
    float& d0, float& d1, float& d2, float& d3,
    uint32_t a0, uint32_t a1, uint32_t a2, uint32_t a3,
    uint32_t b0, uint32_t b1)
{
    asm volatile(
        "mma.sync.aligned.m16n8k16.row.col.f32.f16.f16.f32 "
        "{%0,%1,%2,%3}, {%4,%5,%6,%7}, {%8,%9}, {%0,%1,%2,%3};"
        : "+f"(d0), "+f"(d1), "+f"(d2), "+f"(d3)
        : "r"(a0), "r"(a1), "r"(a2), "r"(a3), "r"(b0), "r"(b1));
}

// ---------------- GEMM: C[NN, OUT] = A[NN,128] @ W[OUT,128]^T (+bias) ------
// Persistent multi-tile fp16 MMA GEMM with cp.async double-buffered A tiles.
template <int OUT, bool HOUT>
__global__ void __launch_bounds__(256, 2) k_gemm(
    const __half* __restrict__ A, const float* __restrict__ W,
    const float* __restrict__ bias, void* __restrict__ Cv)
{
    constexpr int NA = OUT / 16;          // n-atoms per warp (8 or 4)
    constexpr int XWORDS = 128 * 68;
    extern __shared__ uint32_t sm[];      // half2 units
    uint32_t* Xstage[2] = { sm, sm + XWORDS };
    uint32_t* Ws = sm + 2 * XWORDS;       // [OUT][68]
    const int tid  = threadIdx.x;
    const int warp = tid >> 5;
    const int lane = tid & 31;

    const int m_off = (warp >> 1) * 32;        // 0,32,64,96
    const int n_off = (warp & 1) * (OUT / 2);  // 0, OUT/2
    const int gid = lane >> 2;                 // group id 0..7
    const int tig = lane & 3;                  // thread in group 0..3

    auto fill_async = [&](uint32_t* Xs, int t) {
        int row0 = t * 128;
        #pragma unroll
        for (int i = 0; i < 8; i++) {
            int idx = tid + i * 256;
            int r = idx >> 4, c8 = idx & 15;
            uint32_t dst = (uint32_t)__cvta_generic_to_shared(&Xs[r * 68 + c8 * 4]);
            const void* src = (const char*)A + ((size_t)(row0 + r) * 128 + c8 * 8) * 2;
            int sz = (row0 + r < NN) ? 16 : 0;
            asm volatile("cp.async.cg.shared.global [%0], [%1], 16, %2;"
                         :: "r"(dst), "l"(src), "r"(sz));
        }
        asm volatile("cp.async.commit_group;");
    };

    int tile = blockIdx.x;
    if (tile < NTILES) fill_async(Xstage[0], tile);

    for (int idx = tid; idx < OUT * 32; idx += 256) {
        int j = idx >> 5, c4 = idx & 31;
        float4 v = reinterpret_cast<const float4*>(W)[idx];
        uint2 p;
        p.x = pack_h2(v.x, v.y);
        p.y = pack_h2(v.z, v.w);
        *reinterpret_cast<uint2*>(&Ws[j * 68 + c4 * 2]) = p;
    }

    int stage = 0;
    for (; tile < NTILES; tile += GEMM_GRID) {
        int next = tile + GEMM_GRID;
        if (next < NTILES) {
            fill_async(Xstage[stage ^ 1], next);
            asm volatile("cp.async.wait_group 1;");
        } else {
            asm volatile("cp.async.wait_group 0;");
        }
        __syncthreads();
        const uint32_t* Xs = Xstage[stage];
        const int row0 = tile * 128;

        float acc[2][NA][4];
        #pragma unroll
        for (int ma = 0; ma < 2; ma++)
            #pragma unroll
            for (int na = 0; na < NA; na++)
                #pragma unroll
                for (int c = 0; c < 4; c++) acc[ma][na][c] = 0.f;

        #pragma unroll
        for (int ks = 0; ks < 8; ks++) {
            uint32_t a[2][4];
            #pragma unroll
            for (int ma = 0; ma < 2; ma++) {
                int row = m_off + ma * 16 + gid;
                a[ma][0] = Xs[row * 68 + ks * 8 + tig];
                a[ma][1] = Xs[(row + 8) * 68 + ks * 8 + tig];
                a[ma][2] = Xs[row * 68 + ks * 8 + tig + 4];
                a[ma][3] = Xs[(row + 8) * 68 + ks * 8 + tig + 4];
            }
            #pragma unroll
            for (int na = 0; na < NA; na++) {
                int n = n_off + na * 8 + gid;
                uint32_t b0 = Ws[n * 68 + ks * 8 + tig];
                uint32_t b1 = Ws[n * 68 + ks * 8 + tig + 4];
                #pragma unroll
                for (int ma = 0; ma < 2; ma++) {
                    float* d = acc[ma][na];
                    mma_f16(d[0], d[1], d[2], d[3],
                            a[ma][0], a[ma][1], a[ma][2], a[ma][3], b0, b1);
                }
            }
        }

        #pragma unroll
        for (int ma = 0; ma < 2; ma++) {
            #pragma unroll
            for (int na = 0; na < NA; na++) {
                int col = n_off + na * 8 + 2 * tig;
                float bx = 0.f, by = 0.f;
                if (bias) { bx = __ldg(&bias[col]); by = __ldg(&bias[col + 1]); }
                int r0 = row0 + m_off + ma * 16 + gid;
                int r1 = r0 + 8;
                if (HOUT) {
                    __half* C = (__half*)Cv;
                    if (r0 < NN)
                        *reinterpret_cast<__half2*>(&C[(size_t)r0 * OUT + col]) =
                            __floats2half2_rn(acc[ma][na][0] + bx, acc[ma][na][1] + by);
                    if (r1 < NN)
                        *reinterpret_cast<__half2*>(&C[(size_t)r1 * OUT + col]) =
                            __floats2half2_rn(acc[ma][na][2] + bx, acc[ma][na][3] + by);
                } else {
                    float* C = (float*)Cv;
                    if (r0 < NN)
                        *reinterpret_cast<float2*>(&C[(size_t)r0 * OUT + col]) =
                            make_float2(acc[ma][na][0] + bx, acc[ma][na][1] + by);
                    if (r1 < NN)
                        *reinterpret_cast<float2*>(&C[(size_t)r1 * OUT + col]) =
                            make_float2(acc[ma][na][2] + bx, acc[ma][na][3] + by);
                }
            }
        }
        __syncthreads();
        stage ^= 1;
    }
}

// -------- aggregation + self-loop + bias + ReLU fused: warp per node -------
// LDG.128 gather, edge-parity split across lane halves, tail-free.
// Packed fma.rn.f32x2 accumulation (half the FMA-pipe ops), norm shfl'd
// lazily to keep regs <= 64 -> 4 CTAs/SM.
__global__ void __launch_bounds__(256, 4) k_agg_relu(
    const __half* __restrict__ h,
    const float* __restrict__ bias,
    __half* __restrict__ out)
{
    int gw = (blockIdx.x * blockDim.x + threadIdx.x) >> 5;   // node id
    if (gw >= NN) return;
    const int lane = threadIdx.x & 31;
    const int half = lane >> 4;          // edge parity handled by this lane
    const int sub  = lane & 15;          // 16B chunk within the 256B row
    const int beg = g_rowstart[gw];
    const int cnt = g_deg[gw];
    const uint4* hp = reinterpret_cast<const uint4*>(h);     // 16 uint4 / row

    unsigned long long acc64[4];         // 4 x packed float2 accumulators
    #pragma unroll
    for (int d = 0; d < 4; d++) acc64[d] = 0ull;

    for (int t0 = 0; t0 < cnt; t0 += 32) {
        int2 pr = make_int2(0, 0);                 // src=0, norm=0 (inert)
        if (t0 + lane < cnt) pr = __ldg(&g_pair[beg + t0 + lane]);
        int m = min(32, cnt - t0);
        #pragma unroll
        for (int g = 0; g < 2; g++) {
            if (g * 16 >= m) break;
            uint4 u[8];
            #pragma unroll
            for (int q = 0; q < 8; q++) {
                int src = __shfl_sync(0xFFFFFFFFu, pr.x, g * 16 + 2 * q + half);
                u[q] = __ldg(&hp[(size_t)src * 16 + sub]);
            }
            #pragma unroll
            for (int q = 0; q < 8; q++) {
                float nf = __int_as_float(
                    __shfl_sync(0xFFFFFFFFu, pr.y, g * 16 + 2 * q + half));
                unsigned long long n2;
                asm("mov.b64 %0, {%1, %1};" : "=l"(n2) : "f"(nf));
                float2 f0 = __half22float2(*reinterpret_cast<__half2*>(&u[q].x));
                float2 f1 = __half22float2(*reinterpret_cast<__half2*>(&u[q].y));
                float2 f2 = __half22float2(*reinterpret_cast<__half2*>(&u[q].z));
                float2 f3 = __half22float2(*reinterpret_cast<__half2*>(&u[q].w));
                unsigned long long v0, v1, v2, v3;
                asm("mov.b64 %0, {%1, %2};" : "=l"(v0) : "f"(f0.x), "f"(f0.y));
                asm("mov.b64 %0, {%1, %2};" : "=l"(v1) : "f"(f1.x), "f"(f1.y));
                asm("mov.b64 %0, {%1, %2};" : "=l"(v2) : "f"(f2.x), "f"(f2.y));
                asm("mov.b64 %0, {%1, %2};" : "=l"(v3) : "f"(f3.x), "f"(f3.y));
                asm("fma.rn.f32x2 %0, %1, %2, %0;" : "+l"(acc64[0]) : "l"(v0), "l"(n2));
                asm("fma.rn.f32x2 %0, %1, %2, %0;" : "+l"(acc64[1]) : "l"(v1), "l"(n2));
                asm("fma.rn.f32x2 %0, %1, %2, %0;" : "+l"(acc64[2]) : "l"(v2), "l"(n2));
                asm("fma.rn.f32x2 %0, %1, %2, %0;" : "+l"(acc64[3]) : "l"(v3), "l"(n2));
            }
        }
    }

    // unpack accumulators
    float acc[8];
    #pragma unroll
    for (int d = 0; d < 4; d++) {
        asm("mov.b64 {%0, %1}, %2;"
            : "=f"(acc[2 * d]), "=f"(acc[2 * d + 1]) : "l"(acc64[d]));
    }

    // merge the two edge-parity halves: lane l <-> lane l^16 hold same dims
    #pragma unroll
    for (int d = 0; d < 8; d++)
        acc[d] += __shfl_xor_sync(0xFFFFFFFFu, acc[d], 16);

    // self-loop + bias + ReLU; lanes 0-15 write the row
    float dinv_d = g_dinv[gw];
    float c = dinv_d * dinv_d;
    uint4 us = __ldg(&hp[(size_t)gw * 16 + sub]);
    float2 s0 = __half22float2(*reinterpret_cast<__half2*>(&us.x));
    float2 s1 = __half22float2(*reinterpret_cast<__half2*>(&us.y));
    float2 s2 = __half22float2(*reinterpret_cast<__half2*>(&us.z));
    float2 s3 = __half22float2(*reinterpret_cast<__half2*>(&us.w));
    const float4* b4 = reinterpret_cast<const float4*>(bias);
    float4 ba = __ldg(&b4[sub * 2]);
    float4 bb = __ldg(&b4[sub * 2 + 1]);
    float r0 = fmaxf(acc[0] + c * s0.x + ba.x, 0.f);
    float r1 = fmaxf(acc[1] + c * s0.y + ba.y, 0.f);
    float r2 = fmaxf(acc[2] + c * s1.x + ba.z, 0.f);
    float r3 = fmaxf(acc[3] + c * s1.y + ba.w, 0.f);
    float r4 = fmaxf(acc[4] + c * s2.x + bb.x, 0.f);
    float r5 = fmaxf(acc[5] + c * s2.y + bb.y, 0.f);
    float r6 = fmaxf(acc[6] + c * s3.x + bb.z, 0.f);
    float r7 = fmaxf(acc[7] + c * s3.y + bb.w, 0.f);
    if (lane < 16) {
        uint4 o;
        o.x = pack_h2(r0, r1);
        o.y = pack_h2(r2, r3);
        o.z = pack_h2(r4, r5);
        o.w = pack_h2(r6, r7);
        reinterpret_cast<uint4*>(out)[(size_t)gw * 16 + sub] = o;
    }
}

// ---------------- launcher --------------------------------------------------
extern "C" void kernel_launch(void* const* d_in, const int* in_sizes, int n_in,
                              void* d_out, int out_size)
{
    (void)in_sizes; (void)n_in; (void)out_size;
    const float* x  = (const float*)d_in[0];
    const int*   ei = (const int*)d_in[1];          // int32 (JAX x64 disabled)
    const float* W1 = (const float*)d_in[2];
    const float* b1 = (const float*)d_in[3];
    const float* W2 = (const float*)d_in[4];
    const float* b2 = (const float*)d_in[5];
    const float* Wl = (const float*)d_in[6];
    const float* bl = (const float*)d_in[7];
    float* out = (float*)d_out;

    void *pxh, *pbh, *pba, *pdeg, *pcur, *pst;
    cudaGetSymbolAddress(&pxh, g_xh);
    cudaGetSymbolAddress(&pbh, g_bufh);
    cudaGetSymbolAddress(&pba, g_bufact);
    cudaGetSymbolAddress(&pdeg, g_deg);
    cudaGetSymbolAddress(&pcur, g_cursor);
    cudaGetSymbolAddress(&pst,  g_status);
    __half* xh = (__half*)pxh;
    __half* bufh = (__half*)pbh;
    __half* bufact = (__half*)pba;

    const int SMEM128 = (2 * 128 * 68 + 128 * 68) * 4;   // 104448 B
    const int SMEM64  = (2 * 128 * 68 + 64 * 68) * 4;    // 87040 B
    cudaFuncSetAttribute((const void*)k_gemm<128, true>,
                         cudaFuncAttributeMaxDynamicSharedMemorySize, SMEM128);
    cudaFuncSetAttribute((const void*)k_gemm<64, false>,
                         cudaFuncAttributeMaxDynamicSharedMemorySize, SMEM64);

    const int TB = 256;
    const int GB_E = (NE + TB - 1) / TB;           // 6250
    const int GB_W = (NN * 32 + TB - 1) / TB;      // 12500 (warp per node)

    // --- zero-init via memset nodes (not kernel launches) ---
    cudaMemsetAsync(pdeg, 0, NN * sizeof(int));
    cudaMemsetAsync(pcur, 0, NN * sizeof(int));
    cudaMemsetAsync(pst,  0, NB_SCAN * sizeof(int));

    // --- graph preprocessing (fused count+cvt, scan, fill) ---
    k_count_cvt<<<GB_W, TB>>>(ei, (const float4*)x, (uint2*)xh);
    k_scan<<<NB_SCAN, 1024>>>();
    k_fill<<<GB_E, TB>>>(ei);

    // --- layer 1 ---
    k_gemm<128, true><<<GEMM_GRID, TB, SMEM128>>>(xh, W1, nullptr, bufh);
    k_agg_relu<<<GB_W, TB>>>(bufh, b1, bufact);

    // --- layer 2 ---
    k_gemm<128, true><<<GEMM_GRID, TB, SMEM128>>>(bufact, W2, nullptr, bufh);
    k_agg_relu<<<GB_W, TB>>>(bufh, b2, bufact);

    // --- readout ---
    k_gemm<64, false><<<GEMM_GRID, TB, SMEM64>>>(bufact, Wl, bl, out);
}